// round 1
// baseline (speedup 1.0000x reference)
#include <cuda_runtime.h>
#include <math_constants.h>
#include <cstdint>

// Problem constants (fixed shapes from the reference)
constexpr int kB = 2;
constexpr int kC = 32;
constexpr int kH = 32;
constexpr int kW = 256;
constexpr int kN = kH * kW;            // 8192 points per batch
constexpr int kNX = 440;
constexpr int kNY = 500;
constexpr int kNVOX = kNX * kNY;       // 220000
constexpr float PCR0 = 0.0f, PCR1 = -40.0f, PCR2 = -3.0f, PCR5 = 1.0f;
constexpr float VOXS = 0.16f;

// Scratch (allocation-free: __device__ globals)
__device__ float4 g_near[kB * kN];     // compacted valid near pts: x,y,z, bitcast(orig idx)
__device__ float4 g_far [kB * kN];     // compacted valid far pts
__device__ int    g_ncnt[kB];
__device__ int    g_fcnt[kB];
__device__ float  g_cnt [kB * kNVOX];  // per-voxel point counts

// ---------------------------------------------------------------------------
// 1) zero output sums + counts
// ---------------------------------------------------------------------------
__global__ void k_zero(float* __restrict__ out) {
    const int total  = (kB * kC * kNVOX) / 4;  // 3,520,000 float4
    const int ctotal = (kB * kNVOX) / 4;       //   110,000 float4
    float4 z = make_float4(0.f, 0.f, 0.f, 0.f);
    for (int i = blockIdx.x * blockDim.x + threadIdx.x; i < total + ctotal;
         i += gridDim.x * blockDim.x) {
        if (i < total) reinterpret_cast<float4*>(out)[i] = z;
        else           reinterpret_cast<float4*>(g_cnt)[i - total] = z;
    }
}

// ---------------------------------------------------------------------------
// 2) deterministic compaction of valid near + far points (one block per batch)
// ---------------------------------------------------------------------------
__global__ void k_compact(const float* __restrict__ pts,
                          const float* __restrict__ ptsf,
                          const int* __restrict__ m,
                          const int* __restrict__ mf) {
    const int b = blockIdx.x;
    const int t = threadIdx.x;
    constexpr int PER = kN / 256;  // 32 elements per thread, contiguous chunk
    __shared__ int s[256];

    // ---- near ----
    {
        const float* p  = pts + (size_t)b * 4 * kN;
        const int*   mm = m   + (size_t)b * kN;
        int c = 0;
        for (int k = 0; k < PER; ++k) c += (mm[t * PER + k] > 0);
        s[t] = c;
        __syncthreads();
        if (t == 0) {
            int acc = 0;
            for (int i = 0; i < 256; ++i) { int v = s[i]; s[i] = acc; acc += v; }
            g_ncnt[b] = acc;
        }
        __syncthreads();
        int off = s[t];
        for (int k = 0; k < PER; ++k) {
            int n = t * PER + k;
            if (mm[n] > 0) {
                g_near[(size_t)b * kN + off] =
                    make_float4(p[n], p[kN + n], p[2 * kN + n], __int_as_float(n));
                ++off;
            }
        }
        __syncthreads();
    }
    // ---- far ----
    {
        const float* p  = ptsf + (size_t)b * 4 * kN;
        const int*   mm = mf   + (size_t)b * kN;
        int c = 0;
        for (int k = 0; k < PER; ++k) c += (mm[t * PER + k] > 0);
        s[t] = c;
        __syncthreads();
        if (t == 0) {
            int acc = 0;
            for (int i = 0; i < 256; ++i) { int v = s[i]; s[i] = acc; acc += v; }
            g_fcnt[b] = acc;
        }
        __syncthreads();
        int off = s[t];
        for (int k = 0; k < PER; ++k) {
            int n = t * PER + k;
            if (mm[n] > 0) {
                g_far[(size_t)b * kN + off] =
                    make_float4(p[n], p[kN + n], p[2 * kN + n], __int_as_float(n));
                ++off;
            }
        }
    }
}

// ---------------------------------------------------------------------------
// 3) scatter valid near points into output sums + counts
// ---------------------------------------------------------------------------
__global__ void k_scatter_near(const float* __restrict__ fv,
                               const float* __restrict__ pts,
                               const int* __restrict__ m,
                               float* __restrict__ out) {
    int idx = blockIdx.x * blockDim.x + threadIdx.x;
    if (idx >= kB * kN) return;
    int b = idx / kN, n = idx % kN;
    if (m[(size_t)b * kN + n] <= 0) return;
    const float* p = pts + (size_t)b * 4 * kN;
    float x = p[n], y = p[kN + n], z = p[2 * kN + n];
    int ix = (int)floorf((x - PCR0) / VOXS);
    int iy = (int)floorf((y - PCR1) / VOXS);
    if (ix < 0 || ix >= kNX || iy < 0 || iy >= kNY || z < PCR2 || z >= PCR5) return;
    int seg = iy * kNX + ix;
    float* ob = out + (size_t)b * kC * kNVOX + seg;
    const float* f = fv + (size_t)b * kC * kN + n;
#pragma unroll
    for (int c = 0; c < kC; ++c) atomicAdd(ob + (size_t)c * kNVOX, f[(size_t)c * kN]);
    atomicAdd(&g_cnt[(size_t)b * kNVOX + seg], 1.0f);
}

// ---------------------------------------------------------------------------
// 4) 3-NN + inverse-distance interpolation + scatter for valid far points.
//    8 lanes cooperate per far point (lane-local top-3, shfl-xor merge).
// ---------------------------------------------------------------------------
__global__ void k_nn(const float* __restrict__ fv, float* __restrict__ out) {
    const int tid  = blockIdx.x * blockDim.x + threadIdx.x;
    const int g    = tid >> 3;       // subgroup id
    const int lane = tid & 7;
    const int b    = g / kN;
    const int r    = g % kN;

    const int fcnt = g_fcnt[b];
    const bool active = (r < fcnt);
    const int rr = active ? r : 0;

    float4 fp = g_far[(size_t)b * kN + rr];
    const float fx = fp.x, fy = fp.y, fz = fp.z;

    const int V = g_ncnt[b];
    const float4* __restrict__ vp = &g_near[(size_t)b * kN];

    // lane-local sorted top-3 (ascending distance)
    float l0 = CUDART_INF_F, l1 = CUDART_INF_F, l2 = CUDART_INF_F;
    int   j0 = 0x7FFFFFFF,   j1 = 0x7FFFFFFF,   j2 = 0x7FFFFFFF;

    for (int v = lane; v < V; v += 8) {
        float4 p = vp[v];
        float dx = p.x - fx, dy = p.y - fy, dz = p.z - fz;
        float dd = fmaf(dx, dx, fmaf(dy, dy, dz * dz));
        int pi = __float_as_int(p.w);
        if (dd < l2) {
            if (dd < l1) {
                l2 = l1; j2 = j1;
                if (dd < l0) { l1 = l0; j1 = j0; l0 = dd; j0 = pi; }
                else         { l1 = dd; j1 = pi; }
            } else { l2 = dd; j2 = pi; }
        }
    }

    // merge 8 lane-local sorted triples -> global top-3 (3 rounds of min-extract)
    float rd[3];
    int   ri[3];
    int pos = 0;
#pragma unroll
    for (int k = 0; k < 3; ++k) {
        float h  = (pos == 0) ? l0 : (pos == 1) ? l1 : (pos == 2) ? l2 : CUDART_INF_F;
        int   hi = (pos == 0) ? j0 : (pos == 1) ? j1 : (pos == 2) ? j2 : 0x7FFFFFFF;
        float mh = h; int mi = hi;
#pragma unroll
        for (int off = 1; off < 8; off <<= 1) {
            float oh = __shfl_xor_sync(0xFFFFFFFFu, mh, off);
            int   oi = __shfl_xor_sync(0xFFFFFFFFu, mi, off);
            if (oh < mh || (oh == mh && oi < mi)) { mh = oh; mi = oi; }
        }
        rd[k] = mh; ri[k] = mi;
        if (h == mh && hi == mi) ++pos;  // winning lane advances
    }

    // inverse-distance weights (matches reference: recip of squared dist)
    float w0 = 1.0f / (rd[0] + 1e-8f);
    float w1 = 1.0f / (rd[1] + 1e-8f);
    float w2 = 1.0f / (rd[2] + 1e-8f);
    float ws = w0 + w1 + w2;
    w0 /= ws; w1 /= ws; w2 /= ws;

    // clamp gather indices (only hit when <3 valid neighbors; weight is 0 then)
    int u0 = ((unsigned)ri[0] < (unsigned)kN) ? ri[0] : 0;
    int u1 = ((unsigned)ri[1] < (unsigned)kN) ? ri[1] : 0;
    int u2 = ((unsigned)ri[2] < (unsigned)kN) ? ri[2] : 0;

    // voxel bounds for this far point
    int ix = (int)floorf((fx - PCR0) / VOXS);
    int iy = (int)floorf((fy - PCR1) / VOXS);
    bool inb = active && ix >= 0 && ix < kNX && iy >= 0 && iy < kNY &&
               fz >= PCR2 && fz < PCR5;
    int seg = inb ? (iy * kNX + ix) : 0;

    if (active) {
        const float* fb = fv + (size_t)b * kC * kN;
        float* ob = out + (size_t)b * kC * kNVOX;
#pragma unroll
        for (int k = 0; k < 4; ++k) {
            int c = lane + 8 * k;
            const float* fc = fb + (size_t)c * kN;
            float val = w0 * fc[u0] + w1 * fc[u1] + w2 * fc[u2];
            if (inb) atomicAdd(ob + (size_t)c * kNVOX + seg, val);
        }
        if (inb && lane == 0) atomicAdd(&g_cnt[(size_t)b * kNVOX + seg], 1.0f);
    }
}

// ---------------------------------------------------------------------------
// 5) finalize: mean = sum / max(count, 1)
// ---------------------------------------------------------------------------
__global__ void k_fin(float* __restrict__ out) {
    int i = blockIdx.x * blockDim.x + threadIdx.x;
    if (i >= kB * kC * kNVOX) return;
    int v = i % kNVOX;
    int b = i / (kC * kNVOX);
    float c = g_cnt[(size_t)b * kNVOX + v];
    out[i] = out[i] / fmaxf(c, 1.0f);
}

// ---------------------------------------------------------------------------
extern "C" void kernel_launch(void* const* d_in, const int* in_sizes, int n_in,
                              void* d_out, int out_size) {
    const float* fv   = (const float*)d_in[0];  // (B,C,H,W)
    const float* pts  = (const float*)d_in[1];  // (B,4,H,W)
    const float* ptsf = (const float*)d_in[2];  // (B,4,H,W)
    const int*   m    = (const int*)d_in[3];    // (B,H,W)
    const int*   mf   = (const int*)d_in[4];    // (B,H,W)
    float* out = (float*)d_out;                 // (B,C,NY,NX)

    k_zero<<<1024, 256>>>(out);
    k_compact<<<kB, 256>>>(pts, ptsf, m, mf);
    k_scatter_near<<<(kB * kN + 255) / 256, 256>>>(fv, pts, m, out);
    k_nn<<<(kB * kN * 8) / 256, 256>>>(fv, out);
    k_fin<<<(kB * kC * kNVOX + 255) / 256, 256>>>(out);
}

// round 2
// speedup vs baseline: 2.2649x; 2.2649x over previous
#include <cuda_runtime.h>
#include <math_constants.h>
#include <cstdint>

// Problem constants (fixed shapes from the reference)
constexpr int kB = 2;
constexpr int kC = 32;
constexpr int kH = 32;
constexpr int kW = 256;
constexpr int kN = kH * kW;            // 8192 points per batch
constexpr int kNX = 440;
constexpr int kNY = 500;
constexpr int kNVOX = kNX * kNY;       // 220000
constexpr float PCR0 = 0.0f, PCR1 = -40.0f, PCR2 = -3.0f, PCR5 = 1.0f;
constexpr float VOXS = 0.16f;

constexpr int TILE = 2048;             // candidates per smem tile (32 KB)

// Scratch (allocation-free: __device__ globals)
__device__ float4 g_near[kB * kN];     // compacted valid near pts: x,y,z, bitcast(orig idx)
__device__ float4 g_far [kB * kN];     // compacted valid far pts
__device__ int    g_ncnt[kB];
__device__ int    g_fcnt[kB];
__device__ float  g_cnt [kB * kNVOX];  // per-voxel point counts

// ---------------------------------------------------------------------------
// 1) zero output sums + counts
// ---------------------------------------------------------------------------
__global__ void k_zero(float* __restrict__ out) {
    const int total  = (kB * kC * kNVOX) / 4;  // 3,520,000 float4
    const int ctotal = (kB * kNVOX) / 4;       //   110,000 float4
    float4 z = make_float4(0.f, 0.f, 0.f, 0.f);
    for (int i = blockIdx.x * blockDim.x + threadIdx.x; i < total + ctotal;
         i += gridDim.x * blockDim.x) {
        if (i < total) reinterpret_cast<float4*>(out)[i] = z;
        else           reinterpret_cast<float4*>(g_cnt)[i - total] = z;
    }
}

// ---------------------------------------------------------------------------
// 2) deterministic compaction of valid near + far points (one block per batch)
// ---------------------------------------------------------------------------
__global__ void k_compact(const float* __restrict__ pts,
                          const float* __restrict__ ptsf,
                          const int* __restrict__ m,
                          const int* __restrict__ mf) {
    const int b = blockIdx.x;
    const int t = threadIdx.x;
    constexpr int PER = kN / 256;  // 32 elements per thread, contiguous chunk
    __shared__ int s[256];

    // ---- near ----
    {
        const float* p  = pts + (size_t)b * 4 * kN;
        const int*   mm = m   + (size_t)b * kN;
        int c = 0;
        for (int k = 0; k < PER; ++k) c += (mm[t * PER + k] > 0);
        s[t] = c;
        __syncthreads();
        if (t == 0) {
            int acc = 0;
            for (int i = 0; i < 256; ++i) { int v = s[i]; s[i] = acc; acc += v; }
            g_ncnt[b] = acc;
        }
        __syncthreads();
        int off = s[t];
        for (int k = 0; k < PER; ++k) {
            int n = t * PER + k;
            if (mm[n] > 0) {
                g_near[(size_t)b * kN + off] =
                    make_float4(p[n], p[kN + n], p[2 * kN + n], __int_as_float(n));
                ++off;
            }
        }
        __syncthreads();
    }
    // ---- far ----
    {
        const float* p  = ptsf + (size_t)b * 4 * kN;
        const int*   mm = mf   + (size_t)b * kN;
        int c = 0;
        for (int k = 0; k < PER; ++k) c += (mm[t * PER + k] > 0);
        s[t] = c;
        __syncthreads();
        if (t == 0) {
            int acc = 0;
            for (int i = 0; i < 256; ++i) { int v = s[i]; s[i] = acc; acc += v; }
            g_fcnt[b] = acc;
        }
        __syncthreads();
        int off = s[t];
        for (int k = 0; k < PER; ++k) {
            int n = t * PER + k;
            if (mm[n] > 0) {
                g_far[(size_t)b * kN + off] =
                    make_float4(p[n], p[kN + n], p[2 * kN + n], __int_as_float(n));
                ++off;
            }
        }
    }
}

// ---------------------------------------------------------------------------
// 3) scatter valid near points into output sums + counts
// ---------------------------------------------------------------------------
__global__ void k_scatter_near(const float* __restrict__ fv,
                               const float* __restrict__ pts,
                               const int* __restrict__ m,
                               float* __restrict__ out) {
    int idx = blockIdx.x * blockDim.x + threadIdx.x;
    if (idx >= kB * kN) return;
    int b = idx / kN, n = idx % kN;
    if (m[(size_t)b * kN + n] <= 0) return;
    const float* p = pts + (size_t)b * 4 * kN;
    float x = p[n], y = p[kN + n], z = p[2 * kN + n];
    int ix = (int)floorf((x - PCR0) / VOXS);
    int iy = (int)floorf((y - PCR1) / VOXS);
    if (ix < 0 || ix >= kNX || iy < 0 || iy >= kNY || z < PCR2 || z >= PCR5) return;
    int seg = iy * kNX + ix;
    float* ob = out + (size_t)b * kC * kNVOX + seg;
    const float* f = fv + (size_t)b * kC * kN + n;
#pragma unroll
    for (int c = 0; c < kC; ++c) atomicAdd(ob + (size_t)c * kNVOX, f[(size_t)c * kN]);
    atomicAdd(&g_cnt[(size_t)b * kNVOX + seg], 1.0f);
}

// ---------------------------------------------------------------------------
// 4) 3-NN + inverse-distance interpolation + scatter for valid far points.
//    8 lanes per far point; candidates staged in smem tiles; inner loop
//    unrolled x4 with a group-min guard so the common path is branch-free.
// ---------------------------------------------------------------------------
__device__ __forceinline__ void insert3(float dd, int pi,
                                        float& l0, float& l1, float& l2,
                                        int& j0, int& j1, int& j2) {
    if (dd < l2) {
        if (dd < l1) {
            l2 = l1; j2 = j1;
            if (dd < l0) { l1 = l0; j1 = j0; l0 = dd; j0 = pi; }
            else         { l1 = dd; j1 = pi; }
        } else { l2 = dd; j2 = pi; }
    }
}

__global__ void __launch_bounds__(256) k_nn(const float* __restrict__ fv,
                                            float* __restrict__ out) {
    __shared__ float4 sp[TILE];

    const int lane = threadIdx.x & 7;
    const int g    = blockIdx.x * 32 + (threadIdx.x >> 3);  // subgroup id
    const int b    = g / kN;
    const int r    = g % kN;

    const int fcnt = g_fcnt[b];
    const bool active = (r < fcnt);
    const int rr = active ? r : 0;

    float4 fp = g_far[(size_t)b * kN + rr];
    const float fx = fp.x, fy = fp.y, fz = fp.z;

    const int V = g_ncnt[b];
    const float4* __restrict__ vp = &g_near[(size_t)b * kN];

    // lane-local sorted top-3 (ascending distance)
    float l0 = CUDART_INF_F, l1 = CUDART_INF_F, l2 = CUDART_INF_F;
    int   j0 = 0x7FFFFFFF,   j1 = 0x7FFFFFFF,   j2 = 0x7FFFFFFF;

    const float4 sentinel = make_float4(3e37f, 3e37f, 3e37f,
                                        __int_as_float(0x7FFFFFFF));

    for (int base = 0; base < V; base += TILE) {
        // cooperative tile fill (coalesced), sentinel-padded
#pragma unroll
        for (int i = threadIdx.x; i < TILE; i += 256) {
            int v = base + i;
            sp[i] = (v < V) ? vp[v] : sentinel;
        }
        __syncthreads();

#pragma unroll 2
        for (int u = lane; u < TILE; u += 32) {
            float4 p0 = sp[u];
            float4 p1 = sp[u + 8];
            float4 p2 = sp[u + 16];
            float4 p3 = sp[u + 24];
            float dx, dy, dz;
            dx = p0.x - fx; dy = p0.y - fy; dz = p0.z - fz;
            float d0 = fmaf(dx, dx, fmaf(dy, dy, dz * dz));
            dx = p1.x - fx; dy = p1.y - fy; dz = p1.z - fz;
            float d1 = fmaf(dx, dx, fmaf(dy, dy, dz * dz));
            dx = p2.x - fx; dy = p2.y - fy; dz = p2.z - fz;
            float d2 = fmaf(dx, dx, fmaf(dy, dy, dz * dz));
            dx = p3.x - fx; dy = p3.y - fy; dz = p3.z - fz;
            float d3 = fmaf(dx, dx, fmaf(dy, dy, dz * dz));
            float mn = fminf(fminf(d0, d1), fminf(d2, d3));
            if (mn < l2) {  // rare after warm-up
                insert3(d0, __float_as_int(p0.w), l0, l1, l2, j0, j1, j2);
                insert3(d1, __float_as_int(p1.w), l0, l1, l2, j0, j1, j2);
                insert3(d2, __float_as_int(p2.w), l0, l1, l2, j0, j1, j2);
                insert3(d3, __float_as_int(p3.w), l0, l1, l2, j0, j1, j2);
            }
        }
        __syncthreads();
    }

    // merge 8 lane-local sorted triples -> global top-3 (3 rounds of min-extract)
    float rd[3];
    int   ri[3];
    int pos = 0;
#pragma unroll
    for (int k = 0; k < 3; ++k) {
        float h  = (pos == 0) ? l0 : (pos == 1) ? l1 : (pos == 2) ? l2 : CUDART_INF_F;
        int   hi = (pos == 0) ? j0 : (pos == 1) ? j1 : (pos == 2) ? j2 : 0x7FFFFFFF;
        float mh = h; int mi = hi;
#pragma unroll
        for (int off = 1; off < 8; off <<= 1) {
            float oh = __shfl_xor_sync(0xFFFFFFFFu, mh, off);
            int   oi = __shfl_xor_sync(0xFFFFFFFFu, mi, off);
            if (oh < mh || (oh == mh && oi < mi)) { mh = oh; mi = oi; }
        }
        rd[k] = mh; ri[k] = mi;
        if (h == mh && hi == mi) ++pos;  // winning lane advances
    }

    // inverse-distance weights (matches reference: recip of squared dist)
    float w0 = 1.0f / (rd[0] + 1e-8f);
    float w1 = 1.0f / (rd[1] + 1e-8f);
    float w2 = 1.0f / (rd[2] + 1e-8f);
    float ws = w0 + w1 + w2;
    w0 /= ws; w1 /= ws; w2 /= ws;

    // clamp gather indices (only hit when <3 valid neighbors; weight is ~0 then)
    int u0 = ((unsigned)ri[0] < (unsigned)kN) ? ri[0] : 0;
    int u1 = ((unsigned)ri[1] < (unsigned)kN) ? ri[1] : 0;
    int u2 = ((unsigned)ri[2] < (unsigned)kN) ? ri[2] : 0;

    // voxel bounds for this far point
    int ix = (int)floorf((fx - PCR0) / VOXS);
    int iy = (int)floorf((fy - PCR1) / VOXS);
    bool inb = active && ix >= 0 && ix < kNX && iy >= 0 && iy < kNY &&
               fz >= PCR2 && fz < PCR5;
    int seg = inb ? (iy * kNX + ix) : 0;

    if (active) {
        const float* fb = fv + (size_t)b * kC * kN;
        float* ob = out + (size_t)b * kC * kNVOX;
#pragma unroll
        for (int k = 0; k < 4; ++k) {
            int c = lane + 8 * k;
            const float* fc = fb + (size_t)c * kN;
            float val = w0 * fc[u0] + w1 * fc[u1] + w2 * fc[u2];
            if (inb) atomicAdd(ob + (size_t)c * kNVOX + seg, val);
        }
        if (inb && lane == 0) atomicAdd(&g_cnt[(size_t)b * kNVOX + seg], 1.0f);
    }
}

// ---------------------------------------------------------------------------
// 5) sparse finalize: divide only voxels with count > 1 (identity otherwise)
// ---------------------------------------------------------------------------
__global__ void k_fin(float* __restrict__ out) {
    int i = blockIdx.x * blockDim.x + threadIdx.x;
    if (i >= kB * kNVOX) return;
    int b = i / kNVOX, v = i % kNVOX;
    float c = g_cnt[i];
    if (c > 1.0f) {
        float inv = 1.0f / c;
        float* ob = out + (size_t)b * kC * kNVOX + v;
#pragma unroll
        for (int ch = 0; ch < kC; ++ch) ob[(size_t)ch * kNVOX] *= inv;
    }
}

// ---------------------------------------------------------------------------
extern "C" void kernel_launch(void* const* d_in, const int* in_sizes, int n_in,
                              void* d_out, int out_size) {
    const float* fv   = (const float*)d_in[0];  // (B,C,H,W)
    const float* pts  = (const float*)d_in[1];  // (B,4,H,W)
    const float* ptsf = (const float*)d_in[2];  // (B,4,H,W)
    const int*   m    = (const int*)d_in[3];    // (B,H,W)
    const int*   mf   = (const int*)d_in[4];    // (B,H,W)
    float* out = (float*)d_out;                 // (B,C,NY,NX)

    k_zero<<<2048, 256>>>(out);
    k_compact<<<kB, 256>>>(pts, ptsf, m, mf);
    k_scatter_near<<<(kB * kN + 255) / 256, 256>>>(fv, pts, m, out);
    k_nn<<<(kB * kN * 8) / 256, 256>>>(fv, out);
    k_fin<<<(kB * kNVOX + 255) / 256, 256>>>(out);
}